// round 14
// baseline (speedup 1.0000x reference)
#include <cuda_runtime.h>
#include <cuda_bf16.h>
#include <mma.h>
#include <cstdint>

using namespace nvcuda;

#define NN   25000
#define EE   400000
#define FIN  256
#define CC   32
#define AA   9
#define WN   288     // CC*AA
#define BB   8
#define HH   64
#define SSP  4
#define FOUT 256
#define NTIL (EE / 64)   // 6250

__device__ float g_h[NN * CC];      // 3.2 MB
__device__ float g_agg[NN * WN];    // 28.8 MB
__device__ int   g_cnt[NN];
__device__ int   g_perm[EE];
// pre-split Wsc [1024][256] bf16 hi/lo
__device__ __nv_bfloat16 g_Bhi[1024 * 256];
__device__ __nv_bfloat16 g_Blo[1024 * 256];

__device__ __forceinline__ float silu_f(float v) {
    return v / (1.0f + __expf(-v));
}

// ---- packed f32x2 helpers ----
__device__ __forceinline__ void fma2(unsigned long long& acc, unsigned long long a,
                                     unsigned long long b) {
    asm("fma.rn.f32x2 %0, %1, %2, %0;" : "+l"(acc) : "l"(a), "l"(b));
}
__device__ __forceinline__ unsigned long long pack2(float x, float y) {
    unsigned long long r;
    asm("mov.b64 %0, {%1, %2};" : "=l"(r) : "f"(x), "f"(y));
    return r;
}
__device__ __forceinline__ float2 unpack2(unsigned long long v) {
    float2 r;
    asm("mov.b64 {%0, %1}, %2;" : "=f"(r.x), "=f"(r.y) : "l"(v));
    return r;
}
__device__ __forceinline__ unsigned long long lds64(const float* p) {
    return *reinterpret_cast<const unsigned long long*>(p);
}

// ---------------------------------------------------------------------------
__global__ void k_zero() {
    int i = blockIdx.x * blockDim.x + threadIdx.x;
    int stride = gridDim.x * blockDim.x;
    float4* p = (float4*)g_agg;
    const int n4 = (NN * WN) / 4;
    float4 z = make_float4(0.f, 0.f, 0.f, 0.f);
    for (int k = i; k < n4; k += stride) p[k] = z;
    for (int k = i; k < NN; k += stride) g_cnt[k] = 0;
}

// ---------------------------------------------------------------------------
// counting sort by dst
// ---------------------------------------------------------------------------
__global__ void k_hist(const int* __restrict__ dstG) {
    int i = blockIdx.x * blockDim.x + threadIdx.x;
    int stride = gridDim.x * blockDim.x;
    for (int e = i; e < EE; e += stride) atomicAdd(&g_cnt[dstG[e]], 1);
}

__global__ void __launch_bounds__(1024) k_scan() {
    __shared__ int smv[1024];
    const int CH = 25;
    int t = threadIdx.x;
    int base = t * CH;
    int v[CH];
    int s = 0;
#pragma unroll
    for (int i = 0; i < CH; i++) {
        int idx = base + i;
        v[i] = (idx < NN) ? g_cnt[idx] : 0;
        s += v[i];
    }
    smv[t] = s;
    __syncthreads();
    for (int off = 1; off < 1024; off <<= 1) {
        int x = (t >= off) ? smv[t - off] : 0;
        __syncthreads();
        smv[t] += x;
        __syncthreads();
    }
    int ex = (t > 0) ? smv[t - 1] : 0;
#pragma unroll
    for (int i = 0; i < CH; i++) {
        int idx = base + i;
        if (idx < NN) g_cnt[idx] = ex;
        ex += v[i];
    }
}

__global__ void k_place(const int* __restrict__ dstG) {
    int i = blockIdx.x * blockDim.x + threadIdx.x;
    int stride = gridDim.x * blockDim.x;
    for (int e = i; e < EE; e += stride) {
        int pos = atomicAdd(&g_cnt[dstG[e]], 1);
        g_perm[pos] = e;
    }
}

// ---------------------------------------------------------------------------
// h = 0.25 * (x @ W1)    [NN, CC]
// ---------------------------------------------------------------------------
__global__ void __launch_bounds__(256) k_h(const float* __restrict__ x,
                                           const float* __restrict__ W1) {
    __shared__ float sW1[FIN * CC];
    __shared__ float sX[8][FIN];
    int t = threadIdx.x;
    int n0 = blockIdx.x * 8;
    for (int i = t; i < FIN * CC; i += 256) sW1[i] = W1[i];
    for (int i = t; i < 8 * FIN; i += 256)
        sX[i >> 8][i & 255] = x[(n0 + (i >> 8)) * FIN + (i & 255)];
    __syncthreads();
    int ty = t >> 5, tx = t & 31;
    float acc = 0.f;
#pragma unroll 8
    for (int f = 0; f < FIN; f++) acc += sX[ty][f] * sW1[f * CC + tx];
    g_h[(n0 + ty) * CC + tx] = 0.25f * acc;
}

// ---------------------------------------------------------------------------
// weight split for k_sc_mm
// ---------------------------------------------------------------------------
__global__ void k_bsplit(const float* __restrict__ Wsc) {
    int idx = blockIdx.x * blockDim.x + threadIdx.x;
    if (idx >= 1024 * 256) return;
    float v = Wsc[idx];
    __nv_bfloat16 hi = __float2bfloat16(v);
    g_Bhi[idx] = hi;
    g_Blo[idx] = __float2bfloat16(v - __bfloat162float(hi));
}

// ---------------------------------------------------------------------------
// tensor-core k_sc (R8, proven): out = xa @ Wsc, bf16 split
// ---------------------------------------------------------------------------
#define ASTR 40
#define BSTR 264

__global__ void __launch_bounds__(256) k_sc_mm(const float* __restrict__ x,
                                               const float* __restrict__ attrs,
                                               float* __restrict__ out) {
    extern __shared__ char smem[];
    __nv_bfloat16* sAhi = (__nv_bfloat16*)smem;
    __nv_bfloat16* sAlo = sAhi + 64 * ASTR;
    __nv_bfloat16* sBhi = sAlo + 64 * ASTR;
    __nv_bfloat16* sBlo = sBhi + 32 * BSTR;
    float* sOut = (float*)smem;

    int t = threadIdx.x;
    int wid = t >> 5;
    int warp_m = wid >> 2;
    int warp_n = wid & 3;
    int n0 = blockIdx.x * 64;

    wmma::fragment<wmma::accumulator, 16, 16, 16, float> acc[2][4];
#pragma unroll
    for (int im = 0; im < 2; im++)
#pragma unroll
        for (int jn = 0; jn < 4; jn++) wmma::fill_fragment(acc[im][jn], 0.0f);

    for (int kc = 0; kc < FIN * SSP; kc += 32) {
        for (int i = t; i < 64 * 32; i += 256) {
            int n = i >> 5, kk = i & 31;
            int k = kc + kk;
            int nn = n0 + n;
            float a = 0.f;
            if (nn < NN) a = x[nn * FIN + (k >> 2)] * attrs[nn * SSP + (k & 3)];
            __nv_bfloat16 hi = __float2bfloat16(a);
            sAhi[n * ASTR + kk] = hi;
            sAlo[n * ASTR + kk] = __float2bfloat16(a - __bfloat162float(hi));
        }
        for (int i = t; i < 32 * 256; i += 256) {
            int r = i >> 8, c = i & 255;
            sBhi[r * BSTR + c] = g_Bhi[(kc + r) * 256 + c];
            sBlo[r * BSTR + c] = g_Blo[(kc + r) * 256 + c];
        }
        __syncthreads();

#pragma unroll
        for (int kf = 0; kf < 2; kf++) {
            wmma::fragment<wmma::matrix_a, 16, 16, 16, __nv_bfloat16,
                           wmma::row_major> ahi[2], alo[2];
#pragma unroll
            for (int im = 0; im < 2; im++) {
                wmma::load_matrix_sync(ahi[im],
                    sAhi + (warp_m * 32 + 16 * im) * ASTR + kf * 16, ASTR);
                wmma::load_matrix_sync(alo[im],
                    sAlo + (warp_m * 32 + 16 * im) * ASTR + kf * 16, ASTR);
            }
#pragma unroll
            for (int jn = 0; jn < 4; jn++) {
                wmma::fragment<wmma::matrix_b, 16, 16, 16, __nv_bfloat16,
                               wmma::row_major> bhi, blo;
                wmma::load_matrix_sync(bhi,
                    sBhi + (kf * 16) * BSTR + warp_n * 64 + 16 * jn, BSTR);
                wmma::load_matrix_sync(blo,
                    sBlo + (kf * 16) * BSTR + warp_n * 64 + 16 * jn, BSTR);
#pragma unroll
                for (int im = 0; im < 2; im++) {
                    wmma::mma_sync(acc[im][jn], ahi[im], bhi, acc[im][jn]);
                    wmma::mma_sync(acc[im][jn], ahi[im], blo, acc[im][jn]);
                    wmma::mma_sync(acc[im][jn], alo[im], bhi, acc[im][jn]);
                }
            }
        }
        __syncthreads();
    }

    for (int half = 0; half < 2; half++) {
        if (warp_m == half) {
#pragma unroll
            for (int im = 0; im < 2; im++)
#pragma unroll
                for (int jn = 0; jn < 4; jn++)
                    wmma::store_matrix_sync(
                        sOut + (16 * im) * BSTR + warp_n * 64 + 16 * jn,
                        acc[im][jn], BSTR, wmma::mem_row_major);
        }
        __syncthreads();
        for (int i = t; i < 32 * 256; i += 256) {
            int r = i >> 8, c = i & 255;
            int nn = n0 + half * 32 + r;
            if (nn < NN) out[(long long)nn * FOUT + c] = sOut[r * BSTR + c];
        }
        __syncthreads();
    }
}

// ---------------------------------------------------------------------------
// fused edge kernel: 256 threads, 2 CTA/SM, Wm3 via __ldg (L1),
// double-buffered prefetched gathers, merged activation buffer
// ---------------------------------------------------------------------------
#define TSTR 66

__global__ void __launch_bounds__(256, 2) k_edge(
    const float* __restrict__ eeG, const float* __restrict__ shG,
    const int* __restrict__ dstG, const int* __restrict__ srcG,
    const float* __restrict__ Wm1, const float* __restrict__ Wm2,
    const float* __restrict__ Wm3) {
    extern __shared__ float sm[];
    float* sWm1  = sm;                        // 512
    float* sWm2  = sWm1 + 512;                // 4096
    float* sActT = sWm2 + 4096;               // 64*66 = 4224 (h1 then h2, k-major)
    float* sEEb  = sActT + 64 * TSTR;         // 2 x 512
    float* sSHb  = sEEb + 2 * 512;            // 2 x 576
    float* sHsb  = sSHb + 2 * 576;            // 2 x 2048
    int*   sDstb = (int*)(sHsb + 2 * 2048);   // 2 x 64
    int*   sSrcb = sDstb + 128;               // 2 x 64

    int t = threadIdx.x;
    for (int i = t; i < 512;  i += 256) sWm1[i] = Wm1[i];
    for (int i = t; i < 4096; i += 256) sWm2[i] = Wm2[i];

    const int tx = t & 31, ty = t >> 5;
    const int e2 = t >> 2;        // 0..63 (phase 1/2 edge)
    const int q  = t & 3;         // phase 1/2 j-lane (j = q + 4i)

    // prologue: gather tile0 into buffer 0
    {
        int tile0 = blockIdx.x;
        int e0 = tile0 * 64;
        if (t < 64) {
            int eg = g_perm[e0 + t];
            sDstb[t] = dstG[eg];
            sSrcb[t] = srcG[eg];
        }
        for (int i = t; i < 64 * BB; i += 256) {
            int eg = g_perm[e0 + (i >> 3)];
            sEEb[i] = eeG[eg * BB + (i & 7)];
        }
        for (int i = t; i < 64 * AA; i += 256) {
            int e = i / AA;
            int eg = g_perm[e0 + e];
            sSHb[i] = shG[eg * AA + (i - AA * e)];
        }
        for (int i = t; i < 64 * CC; i += 256) {
            int eg = g_perm[e0 + (i >> 5)];
            sHsb[i] = g_h[srcG[eg] * CC + (i & 31)];
        }
    }
    __syncthreads();

    int p = 0;
    for (int tile = blockIdx.x; tile < NTIL; tile += gridDim.x, p ^= 1) {
        const float* sEE = sEEb + p * 512;
        const float* sSH = sSHb + p * 576;
        const float* sHs = sHsb + p * 2048;
        const int*   sDst = sDstb + p * 64;

        // prefetch tile+grid into the other buffer (no barrier: consumed next iter)
        int ntile = tile + gridDim.x;
        if (ntile < NTIL) {
            int e1 = ntile * 64;
            float* dEE = sEEb + (p ^ 1) * 512;
            float* dSH = sSHb + (p ^ 1) * 576;
            float* dHs = sHsb + (p ^ 1) * 2048;
            int* dDst = sDstb + (p ^ 1) * 64;
            int* dSrc = sSrcb + (p ^ 1) * 64;
            if (t < 64) {
                int eg = g_perm[e1 + t];
                dDst[t] = dstG[eg];
                dSrc[t] = srcG[eg];
            }
            for (int i = t; i < 64 * BB; i += 256) {
                int eg = g_perm[e1 + (i >> 3)];
                dEE[i] = eeG[eg * BB + (i & 7)];
            }
            for (int i = t; i < 64 * AA; i += 256) {
                int e = i / AA;
                int eg = g_perm[e1 + e];
                dSH[i] = shG[eg * AA + (i - AA * e)];
            }
            for (int i = t; i < 64 * CC; i += 256) {
                int eg = g_perm[e1 + (i >> 5)];
                dHs[i] = g_h[srcG[eg] * CC + (i & 31)];
            }
        }

        // phase 1: h1 = silu(ee @ Wm1), written transposed sActT[j][e]
        {
            float acc[16];
#pragma unroll
            for (int i = 0; i < 16; i++) acc[i] = 0.f;
#pragma unroll
            for (int b = 0; b < BB; b++) {
                float v = sEE[e2 * BB + b];
#pragma unroll
                for (int i = 0; i < 16; i++) acc[i] += v * sWm1[b * HH + q + 4 * i];
            }
#pragma unroll
            for (int i = 0; i < 16; i++)
                sActT[(q + 4 * i) * TSTR + e2] = silu_f(acc[i]);
        }
        __syncthreads();

        // phase 2: h2 = silu(h1 @ Wm2); read ALL h1 -> regs, barrier, overwrite
        {
            float acc[16];
#pragma unroll
            for (int i = 0; i < 16; i++) acc[i] = 0.f;
#pragma unroll 8
            for (int k = 0; k < HH; k++) {
                float v = sActT[k * TSTR + e2];
#pragma unroll
                for (int i = 0; i < 16; i++) acc[i] += v * sWm2[k * HH + q + 4 * i];
            }
            __syncthreads();
#pragma unroll
            for (int i = 0; i < 16; i++)
                sActT[(q + 4 * i) * TSTR + e2] = silu_f(acc[i]);
        }
        __syncthreads();

        // phase 3: edge-pair FFMA2; B = Wm3 via __ldg (L1-resident)
        {
            unsigned long long acc2[4][9];
#pragma unroll
            for (int m = 0; m < 4; m++)
#pragma unroll
                for (int j = 0; j < 9; j++) acc2[m][j] = 0ull;

#pragma unroll 2
            for (int k = 0; k < HH; k++) {
                unsigned long long a2[4];
#pragma unroll
                for (int m = 0; m < 4; m++)
                    a2[m] = lds64(&sActT[k * TSTR + 8 * ty + 2 * m]);
#pragma unroll
                for (int j = 0; j < 9; j++) {
                    float b = __ldg(&Wm3[k * WN + tx + 32 * j]);
                    unsigned long long bb = pack2(b, b);
#pragma unroll
                    for (int m = 0; m < 4; m++) fma2(acc2[m][j], a2[m], bb);
                }
            }

            // epilogue: run-length reduce + scatter (c,a via mul-shift /9)
            float racc[9];
            int cjl[9], ajl[9];
#pragma unroll
            for (int j = 0; j < 9; j++) {
                racc[j] = 0.f;
                int o = tx + 32 * j;
                int c = (o * 7282) >> 16;   // floor(o/9) for o<512
                cjl[j] = c;
                ajl[j] = o - 9 * c;
            }
            int cur = sDst[8 * ty];

#pragma unroll
            for (int m = 0; m < 4; m++) {
                int e0 = 8 * ty + 2 * m;
                int e1 = e0 + 1;
                const float* hs0 = &sHs[e0 * CC];
                const float* hs1 = &sHs[e1 * CC];
                const float* sh0 = &sSH[e0 * AA];
                const float* sh1 = &sSH[e1 * AA];
                int d0 = sDst[e0], d1 = sDst[e1];
                if (d0 != cur) {
                    float* dp = g_agg + (long long)cur * WN;
#pragma unroll
                    for (int j = 0; j < 9; j++) {
                        atomicAdd(dp + tx + 32 * j, racc[j]);
                        racc[j] = 0.f;
                    }
                    cur = d0;
                }
#pragma unroll
                for (int j = 0; j < 9; j++) {
                    float2 w = unpack2(acc2[m][j]);
                    racc[j] += w.x * hs0[cjl[j]] * sh0[ajl[j]];
                }
                if (d1 != cur) {
                    float* dp = g_agg + (long long)cur * WN;
#pragma unroll
                    for (int j = 0; j < 9; j++) {
                        atomicAdd(dp + tx + 32 * j, racc[j]);
                        racc[j] = 0.f;
                    }
                    cur = d1;
                }
#pragma unroll
                for (int j = 0; j < 9; j++) {
                    float2 w = unpack2(acc2[m][j]);
                    racc[j] += w.y * hs1[cjl[j]] * sh1[ajl[j]];
                }
            }
            {
                float* dp = g_agg + (long long)cur * WN;
#pragma unroll
                for (int j = 0; j < 9; j++) atomicAdd(dp + tx + 32 * j, racc[j]);
            }
        }
        __syncthreads();   // end-of-tile: protects sActT reuse + prefetch visibility
    }
}

// ---------------------------------------------------------------------------
// out = silu(agg @ W2) + sc_out (R1 scalar, proven)
// ---------------------------------------------------------------------------
__global__ void __launch_bounds__(256) k_final(const float* __restrict__ W2,
                                               float* __restrict__ out) {
    __shared__ float sA[32][65];
    __shared__ float sB[32][64];
    int t = threadIdx.x;
    int n0 = blockIdx.x * 64;
    int o0 = blockIdx.y * 64;
    int tr = t >> 4, tc = t & 15;
    float acc[4][4];
#pragma unroll
    for (int i = 0; i < 4; i++)
#pragma unroll
        for (int j = 0; j < 4; j++) acc[i][j] = 0.f;

    for (int kc = 0; kc < WN; kc += 32) {
        for (int i = t; i < 64 * 32; i += 256) {
            int n = i >> 5, kk = i & 31;
            int nn = n0 + n;
            sA[kk][n] = (nn < NN) ? g_agg[(long long)nn * WN + kc + kk] : 0.f;
        }
        for (int i = t; i < 32 * 64; i += 256) {
            int kk = i >> 6, o = i & 63;
            sB[kk][o] = W2[(kc + kk) * FOUT + o0 + o];
        }
        __syncthreads();
#pragma unroll 8
        for (int k = 0; k < 32; k++) {
            float a[4], b[4];
#pragma unroll
            for (int i = 0; i < 4; i++) a[i] = sA[k][tr * 4 + i];
#pragma unroll
            for (int j = 0; j < 4; j++) b[j] = sB[k][tc * 4 + j];
#pragma unroll
            for (int i = 0; i < 4; i++)
#pragma unroll
                for (int j = 0; j < 4; j++) acc[i][j] += a[i] * b[j];
        }
        __syncthreads();
    }
#pragma unroll
    for (int i = 0; i < 4; i++) {
        int nn = n0 + tr * 4 + i;
        if (nn >= NN) continue;
#pragma unroll
        for (int j = 0; j < 4; j++) {
            int o = o0 + tc * 4 + j;
            out[nn * FOUT + o] = silu_f(acc[i][j]) + out[nn * FOUT + o];
        }
    }
}

// ---------------------------------------------------------------------------
extern "C" void kernel_launch(void* const* d_in, const int* in_sizes, int n_in,
                              void* d_out, int out_size) {
    const float* x     = (const float*)d_in[0];
    const float* attrs = (const float*)d_in[1];
    const float* ee    = (const float*)d_in[2];
    const float* sh    = (const float*)d_in[3];
    const int*   eidx  = (const int*)d_in[4];
    const float* W1    = (const float*)d_in[5];
    const float* Wm1   = (const float*)d_in[6];
    const float* Wm2   = (const float*)d_in[7];
    const float* Wm3   = (const float*)d_in[8];
    const float* W2    = (const float*)d_in[9];
    const float* Wsc   = (const float*)d_in[10];
    float* out = (float*)d_out;

    const int* dst = eidx;
    const int* src = eidx + EE;

    k_zero<<<1024, 256>>>();
    k_hist<<<400, 256>>>(dst);
    k_scan<<<1, 1024>>>();
    k_place<<<400, 256>>>(dst);

    k_h<<<NN / 8, 256>>>(x, W1);
    k_bsplit<<<1024, 256>>>(Wsc);

    const int sc_smem = (2 * 64 * ASTR + 2 * 32 * BSTR) * 2 + 256;
    cudaFuncSetAttribute(k_sc_mm, cudaFuncAttributeMaxDynamicSharedMemorySize, sc_smem);
    k_sc_mm<<<(NN + 63) / 64, 256, sc_smem>>>(x, attrs, out);

    const int edge_smem =
        (512 + 4096 + 64 * TSTR + 2 * 512 + 2 * 576 + 2 * 2048) * 4 +
        4 * 64 * 4 + 64;
    cudaFuncSetAttribute(k_edge, cudaFuncAttributeMaxDynamicSharedMemorySize, edge_smem);
    k_edge<<<304, 256, edge_smem>>>(ee, sh, dst, src, Wm1, Wm2, Wm3);

    dim3 gf((NN + 63) / 64, 4);
    k_final<<<gf, 256>>>(W2, out);
}

// round 16
// speedup vs baseline: 1.2669x; 1.2669x over previous
#include <cuda_runtime.h>
#include <cuda_bf16.h>
#include <mma.h>
#include <cstdint>

using namespace nvcuda;

#define NN   25000
#define EE   400000
#define FIN  256
#define CC   32
#define AA   9
#define WN   288     // CC*AA
#define BB   8
#define HH   64
#define SSP  4
#define FOUT 256

__device__ float g_h[NN * CC];      // 3.2 MB
__device__ float g_agg[NN * WN];    // 28.8 MB
__device__ int   g_cnt[NN];
__device__ int   g_perm[EE];
// pre-split Wsc [1024][256] bf16 hi/lo
__device__ __nv_bfloat16 g_Bhi[1024 * 256];
__device__ __nv_bfloat16 g_Blo[1024 * 256];

__device__ __forceinline__ float silu_f(float v) {
    return v / (1.0f + __expf(-v));
}

// ---- packed f32x2 helpers ----
__device__ __forceinline__ void fma2(unsigned long long& acc, unsigned long long a,
                                     unsigned long long b) {
    asm("fma.rn.f32x2 %0, %1, %2, %0;" : "+l"(acc) : "l"(a), "l"(b));
}
__device__ __forceinline__ unsigned long long pack2(float x, float y) {
    unsigned long long r;
    asm("mov.b64 %0, {%1, %2};" : "=l"(r) : "f"(x), "f"(y));
    return r;
}
__device__ __forceinline__ float2 unpack2(unsigned long long v) {
    float2 r;
    asm("mov.b64 {%0, %1}, %2;" : "=f"(r.x), "=f"(r.y) : "l"(v));
    return r;
}
__device__ __forceinline__ unsigned long long lds64(const float* p) {
    return *reinterpret_cast<const unsigned long long*>(p);
}

// ---- cp.async helpers ----
__device__ __forceinline__ void cp16(void* dst_smem, const void* src_gmem) {
    unsigned sdst = (unsigned)__cvta_generic_to_shared(dst_smem);
    asm volatile("cp.async.cg.shared.global [%0], [%1], 16;"
                 :: "r"(sdst), "l"(src_gmem) : "memory");
}
__device__ __forceinline__ void cp_wait_all() {
    asm volatile("cp.async.commit_group;\ncp.async.wait_group 0;" ::: "memory");
}

// ---------------------------------------------------------------------------
__global__ void k_zero() {
    int i = blockIdx.x * blockDim.x + threadIdx.x;
    int stride = gridDim.x * blockDim.x;
    float4* p = (float4*)g_agg;
    const int n4 = (NN * WN) / 4;
    float4 z = make_float4(0.f, 0.f, 0.f, 0.f);
    for (int k = i; k < n4; k += stride) p[k] = z;
    for (int k = i; k < NN; k += stride) g_cnt[k] = 0;
}

// ---------------------------------------------------------------------------
// counting sort by dst
// ---------------------------------------------------------------------------
__global__ void k_hist(const int* __restrict__ dstG) {
    int i = blockIdx.x * blockDim.x + threadIdx.x;
    int stride = gridDim.x * blockDim.x;
    for (int e = i; e < EE; e += stride) atomicAdd(&g_cnt[dstG[e]], 1);
}

__global__ void __launch_bounds__(1024) k_scan() {
    __shared__ int smv[1024];
    const int CH = 25;
    int t = threadIdx.x;
    int base = t * CH;
    int v[CH];
    int s = 0;
#pragma unroll
    for (int i = 0; i < CH; i++) {
        int idx = base + i;
        v[i] = (idx < NN) ? g_cnt[idx] : 0;
        s += v[i];
    }
    smv[t] = s;
    __syncthreads();
    for (int off = 1; off < 1024; off <<= 1) {
        int x = (t >= off) ? smv[t - off] : 0;
        __syncthreads();
        smv[t] += x;
        __syncthreads();
    }
    int ex = (t > 0) ? smv[t - 1] : 0;
#pragma unroll
    for (int i = 0; i < CH; i++) {
        int idx = base + i;
        if (idx < NN) g_cnt[idx] = ex;
        ex += v[i];
    }
}

__global__ void k_place(const int* __restrict__ dstG) {
    int i = blockIdx.x * blockDim.x + threadIdx.x;
    int stride = gridDim.x * blockDim.x;
    for (int e = i; e < EE; e += stride) {
        int pos = atomicAdd(&g_cnt[dstG[e]], 1);
        g_perm[pos] = e;
    }
}

// ---------------------------------------------------------------------------
// h = 0.25 * (x @ W1)    [NN, CC]
// ---------------------------------------------------------------------------
__global__ void __launch_bounds__(256) k_h(const float* __restrict__ x,
                                           const float* __restrict__ W1) {
    __shared__ float sW1[FIN * CC];
    __shared__ float sX[8][FIN];
    int t = threadIdx.x;
    int n0 = blockIdx.x * 8;
    for (int i = t; i < FIN * CC; i += 256) sW1[i] = W1[i];
    for (int i = t; i < 8 * FIN; i += 256)
        sX[i >> 8][i & 255] = x[(n0 + (i >> 8)) * FIN + (i & 255)];
    __syncthreads();
    int ty = t >> 5, tx = t & 31;
    float acc = 0.f;
#pragma unroll 8
    for (int f = 0; f < FIN; f++) acc += sX[ty][f] * sW1[f * CC + tx];
    g_h[(n0 + ty) * CC + tx] = 0.25f * acc;
}

// ---------------------------------------------------------------------------
// weight split for k_sc_mm
// ---------------------------------------------------------------------------
__global__ void k_bsplit(const float* __restrict__ Wsc) {
    int idx = blockIdx.x * blockDim.x + threadIdx.x;
    if (idx >= 1024 * 256) return;
    float v = Wsc[idx];
    __nv_bfloat16 hi = __float2bfloat16(v);
    g_Bhi[idx] = hi;
    g_Blo[idx] = __float2bfloat16(v - __bfloat162float(hi));
}

// ---------------------------------------------------------------------------
// tensor-core k_sc (R8 structure + cp.async B staging): out = xa @ Wsc
// ---------------------------------------------------------------------------
#define ASTR 40
#define BSTR 264

__global__ void __launch_bounds__(256) k_sc_mm(const float* __restrict__ x,
                                               const float* __restrict__ attrs,
                                               float* __restrict__ out) {
    extern __shared__ char smem[];
    __nv_bfloat16* sAhi = (__nv_bfloat16*)smem;
    __nv_bfloat16* sAlo = sAhi + 64 * ASTR;
    __nv_bfloat16* sBhi = sAlo + 64 * ASTR;
    __nv_bfloat16* sBlo = sBhi + 32 * BSTR;
    float* sOut = (float*)smem;

    int t = threadIdx.x;
    int wid = t >> 5;
    int warp_m = wid >> 2;
    int warp_n = wid & 3;
    int n0 = blockIdx.x * 64;

    wmma::fragment<wmma::accumulator, 16, 16, 16, float> acc[2][4];
#pragma unroll
    for (int im = 0; im < 2; im++)
#pragma unroll
        for (int jn = 0; jn < 4; jn++) wmma::fill_fragment(acc[im][jn], 0.0f);

    for (int kc = 0; kc < FIN * SSP; kc += 32) {
        // B staging via cp.async (issued first; latency hides under A staging)
        // 32 rows x 256 bf16 = 32 x 32 16B-chunks per matrix
#pragma unroll
        for (int q = 0; q < 4; q++) {
            int i = t + 256 * q;            // 0..1023
            int r = i >> 5, cc = i & 31;    // row, 16B-chunk
            cp16(sBhi + r * BSTR + cc * 8, g_Bhi + (kc + r) * 256 + cc * 8);
            cp16(sBlo + r * BSTR + cc * 8, g_Blo + (kc + r) * 256 + cc * 8);
        }
        // A staging: xa[n,k] = x[n,k>>2]*attrs[n,k&3], split hi/lo
        for (int i = t; i < 64 * 32; i += 256) {
            int n = i >> 5, kk = i & 31;
            int k = kc + kk;
            int nn = n0 + n;
            float a = 0.f;
            if (nn < NN) a = x[nn * FIN + (k >> 2)] * attrs[nn * SSP + (k & 3)];
            __nv_bfloat16 hi = __float2bfloat16(a);
            sAhi[n * ASTR + kk] = hi;
            sAlo[n * ASTR + kk] = __float2bfloat16(a - __bfloat162float(hi));
        }
        cp_wait_all();
        __syncthreads();

#pragma unroll
        for (int kf = 0; kf < 2; kf++) {
            wmma::fragment<wmma::matrix_a, 16, 16, 16, __nv_bfloat16,
                           wmma::row_major> ahi[2], alo[2];
#pragma unroll
            for (int im = 0; im < 2; im++) {
                wmma::load_matrix_sync(ahi[im],
                    sAhi + (warp_m * 32 + 16 * im) * ASTR + kf * 16, ASTR);
                wmma::load_matrix_sync(alo[im],
                    sAlo + (warp_m * 32 + 16 * im) * ASTR + kf * 16, ASTR);
            }
#pragma unroll
            for (int jn = 0; jn < 4; jn++) {
                wmma::fragment<wmma::matrix_b, 16, 16, 16, __nv_bfloat16,
                               wmma::row_major> bhi, blo;
                wmma::load_matrix_sync(bhi,
                    sBhi + (kf * 16) * BSTR + warp_n * 64 + 16 * jn, BSTR);
                wmma::load_matrix_sync(blo,
                    sBlo + (kf * 16) * BSTR + warp_n * 64 + 16 * jn, BSTR);
#pragma unroll
                for (int im = 0; im < 2; im++) {
                    wmma::mma_sync(acc[im][jn], ahi[im], bhi, acc[im][jn]);
                    wmma::mma_sync(acc[im][jn], ahi[im], blo, acc[im][jn]);
                    wmma::mma_sync(acc[im][jn], alo[im], bhi, acc[im][jn]);
                }
            }
        }
        __syncthreads();
    }

    for (int half = 0; half < 2; half++) {
        if (warp_m == half) {
#pragma unroll
            for (int im = 0; im < 2; im++)
#pragma unroll
                for (int jn = 0; jn < 4; jn++)
                    wmma::store_matrix_sync(
                        sOut + (16 * im) * BSTR + warp_n * 64 + 16 * jn,
                        acc[im][jn], BSTR, wmma::mem_row_major);
        }
        __syncthreads();
        for (int i = t; i < 32 * 256; i += 256) {
            int r = i >> 8, c = i & 255;
            int nn = n0 + half * 32 + r;
            if (nn < NN) out[(long long)nn * FOUT + c] = sOut[r * BSTR + c];
        }
        __syncthreads();
    }
}

// ---------------------------------------------------------------------------
// fused edge kernel (R13, proven): 256 threads, 2 CTA/SM, Wm3 via __ldg (L1)
// ---------------------------------------------------------------------------
#define ACTP 65
#define TSTR 66

__global__ void __launch_bounds__(256, 2) k_edge(
    const float* __restrict__ eeG, const float* __restrict__ shG,
    const int* __restrict__ dstG, const int* __restrict__ srcG,
    const float* __restrict__ Wm1, const float* __restrict__ Wm2,
    const float* __restrict__ Wm3) {
    extern __shared__ float sm[];
    float* sWm1  = sm;                       // 512
    float* sWm2  = sWm1 + 512;               // 4096
    float* sAct  = sWm2 + 4096;              // 64*65
    float* sActT = sAct + 64 * ACTP;         // 64*66
    float* sEE   = sActT + 64 * TSTR;        // 512
    float* sSH   = sEE + 512;                // 576
    float* sHs   = sSH + 576;                // 2048
    int*   sDst  = (int*)(sHs + 2048);       // 64
    int*   sSrc  = sDst + 64;                // 64
    int*   sEid  = sSrc + 64;                // 64

    int t = threadIdx.x;
    for (int i = t; i < 512;  i += 256) sWm1[i] = Wm1[i];
    for (int i = t; i < 4096; i += 256) sWm2[i] = Wm2[i];
    __syncthreads();

    const int tx = t & 31, ty = t >> 5;
    const int e_loc = t & 63;
    const int j0 = (t >> 6) * 16;

    for (int tile = blockIdx.x; tile < EE / 64; tile += gridDim.x) {
        int e0g = tile * 64;
        if (t < 64) {
            int eg = g_perm[e0g + t];
            sEid[t] = eg;
            sDst[t] = dstG[eg];
            sSrc[t] = srcG[eg];
        }
        __syncthreads();
        for (int i = t; i < 64 * BB; i += 256) {
            int e = i >> 3, b = i & 7;
            sEE[i] = eeG[sEid[e] * BB + b];
        }
        for (int i = t; i < 64 * AA; i += 256) {
            int e = i / AA, a = i - AA * e;
            sSH[i] = shG[sEid[e] * AA + a];
        }
        for (int i = t; i < 64 * CC; i += 256) {
            int e = i >> 5, c = i & 31;
            sHs[i] = g_h[sSrc[e] * CC + c];
        }
        __syncthreads();

        // phase 1: h1 = silu(ee @ Wm1)
        {
            float acc[16];
#pragma unroll
            for (int j = 0; j < 16; j++) acc[j] = 0.f;
#pragma unroll
            for (int b = 0; b < BB; b++) {
                float v = sEE[e_loc * BB + b];
#pragma unroll
                for (int j = 0; j < 16; j++) acc[j] += v * sWm1[b * HH + j0 + j];
            }
#pragma unroll
            for (int j = 0; j < 16; j++) sAct[e_loc * ACTP + j0 + j] = silu_f(acc[j]);
        }
        __syncthreads();

        // phase 2: h2 = silu(h1 @ Wm2), transposed output
        {
            float acc[16];
#pragma unroll
            for (int j = 0; j < 16; j++) acc[j] = 0.f;
#pragma unroll 8
            for (int k = 0; k < HH; k++) {
                float v = sAct[e_loc * ACTP + k];
#pragma unroll
                for (int j = 0; j < 16; j++) acc[j] += v * sWm2[k * HH + j0 + j];
            }
#pragma unroll
            for (int j = 0; j < 16; j++)
                sActT[(j0 + j) * TSTR + e_loc] = silu_f(acc[j]);
        }
        __syncthreads();

        // phase 3: edge-pair FFMA2; B = Wm3 via __ldg (L1-resident, coalesced)
        {
            unsigned long long acc2[4][9];
#pragma unroll
            for (int m = 0; m < 4; m++)
#pragma unroll
                for (int j = 0; j < 9; j++) acc2[m][j] = 0ull;

#pragma unroll 2
            for (int k = 0; k < HH; k++) {
                unsigned long long a2[4];
#pragma unroll
                for (int m = 0; m < 4; m++)
                    a2[m] = lds64(&sActT[k * TSTR + 8 * ty + 2 * m]);
#pragma unroll
                for (int j = 0; j < 9; j++) {
                    float b = __ldg(&Wm3[k * WN + tx + 32 * j]);
                    unsigned long long bb = pack2(b, b);
#pragma unroll
                    for (int m = 0; m < 4; m++) fma2(acc2[m][j], a2[m], bb);
                }
            }

            // epilogue: run-length reduce + scatter (c,a via mul-shift /9)
            float racc[9];
            int cjl[9], ajl[9];
#pragma unroll
            for (int j = 0; j < 9; j++) {
                racc[j] = 0.f;
                int o = tx + 32 * j;
                int c = (o * 7282) >> 16;   // floor(o/9) for o<512
                cjl[j] = c;
                ajl[j] = o - 9 * c;
            }
            int cur = sDst[8 * ty];

#pragma unroll
            for (int m = 0; m < 4; m++) {
                int e0 = 8 * ty + 2 * m;
                int e1 = e0 + 1;
                const float* hs0 = &sHs[e0 * CC];
                const float* hs1 = &sHs[e1 * CC];
                const float* sh0 = &sSH[e0 * AA];
                const float* sh1 = &sSH[e1 * AA];
                int d0 = sDst[e0], d1 = sDst[e1];
                if (d0 != cur) {
                    float* dp = g_agg + (long long)cur * WN;
#pragma unroll
                    for (int j = 0; j < 9; j++) {
                        atomicAdd(dp + tx + 32 * j, racc[j]);
                        racc[j] = 0.f;
                    }
                    cur = d0;
                }
#pragma unroll
                for (int j = 0; j < 9; j++) {
                    float2 w = unpack2(acc2[m][j]);
                    racc[j] += w.x * hs0[cjl[j]] * sh0[ajl[j]];
                }
                if (d1 != cur) {
                    float* dp = g_agg + (long long)cur * WN;
#pragma unroll
                    for (int j = 0; j < 9; j++) {
                        atomicAdd(dp + tx + 32 * j, racc[j]);
                        racc[j] = 0.f;
                    }
                    cur = d1;
                }
#pragma unroll
                for (int j = 0; j < 9; j++) {
                    float2 w = unpack2(acc2[m][j]);
                    racc[j] += w.y * hs1[cjl[j]] * sh1[ajl[j]];
                }
            }
            {
                float* dp = g_agg + (long long)cur * WN;
#pragma unroll
                for (int j = 0; j < 9; j++) atomicAdd(dp + tx + 32 * j, racc[j]);
            }
        }
        __syncthreads();
    }
}

// ---------------------------------------------------------------------------
// out = silu(agg @ W2) + sc_out (R1 scalar, proven)
// ---------------------------------------------------------------------------
__global__ void __launch_bounds__(256) k_final(const float* __restrict__ W2,
                                               float* __restrict__ out) {
    __shared__ float sA[32][65];
    __shared__ float sB[32][64];
    int t = threadIdx.x;
    int n0 = blockIdx.x * 64;
    int o0 = blockIdx.y * 64;
    int tr = t >> 4, tc = t & 15;
    float acc[4][4];
#pragma unroll
    for (int i = 0; i < 4; i++)
#pragma unroll
        for (int j = 0; j < 4; j++) acc[i][j] = 0.f;

    for (int kc = 0; kc < WN; kc += 32) {
        for (int i = t; i < 64 * 32; i += 256) {
            int n = i >> 5, kk = i & 31;
            int nn = n0 + n;
            sA[kk][n] = (nn < NN) ? g_agg[(long long)nn * WN + kc + kk] : 0.f;
        }
        for (int i = t; i < 32 * 64; i += 256) {
            int kk = i >> 6, o = i & 63;
            sB[kk][o] = W2[(kc + kk) * FOUT + o0 + o];
        }
        __syncthreads();
#pragma unroll 8
        for (int k = 0; k < 32; k++) {
            float a[4], b[4];
#pragma unroll
            for (int i = 0; i < 4; i++) a[i] = sA[k][tr * 4 + i];
#pragma unroll
            for (int j = 0; j < 4; j++) b[j] = sB[k][tc * 4 + j];
#pragma unroll
            for (int i = 0; i < 4; i++)
#pragma unroll
                for (int j = 0; j < 4; j++) acc[i][j] += a[i] * b[j];
        }
        __syncthreads();
    }
#pragma unroll
    for (int i = 0; i < 4; i++) {
        int nn = n0 + tr * 4 + i;
        if (nn >= NN) continue;
#pragma unroll
        for (int j = 0; j < 4; j++) {
            int o = o0 + tc * 4 + j;
            out[nn * FOUT + o] = silu_f(acc[i][j]) + out[nn * FOUT + o];
        }
    }
}

// ---------------------------------------------------------------------------
extern "C" void kernel_launch(void* const* d_in, const int* in_sizes, int n_in,
                              void* d_out, int out_size) {
    const float* x     = (const float*)d_in[0];
    const float* attrs = (const float*)d_in[1];
    const float* ee    = (const float*)d_in[2];
    const float* sh    = (const float*)d_in[3];
    const int*   eidx  = (const int*)d_in[4];
    const float* W1    = (const float*)d_in[5];
    const float* Wm1   = (const float*)d_in[6];
    const float* Wm2   = (const float*)d_in[7];
    const float* Wm3   = (const float*)d_in[8];
    const float* W2    = (const float*)d_in[9];
    const float* Wsc   = (const float*)d_in[10];
    float* out = (float*)d_out;

    const int* dst = eidx;
    const int* src = eidx + EE;

    k_zero<<<1024, 256>>>();
    k_hist<<<400, 256>>>(dst);
    k_scan<<<1, 1024>>>();
    k_place<<<400, 256>>>(dst);

    k_h<<<NN / 8, 256>>>(x, W1);
    k_bsplit<<<1024, 256>>>(Wsc);

    const int sc_smem = (2 * 64 * ASTR + 2 * 32 * BSTR) * 2 + 256;
    cudaFuncSetAttribute(k_sc_mm, cudaFuncAttributeMaxDynamicSharedMemorySize, sc_smem);
    k_sc_mm<<<(NN + 63) / 64, 256, sc_smem>>>(x, attrs, out);

    const int edge_smem =
        (512 + 4096 + 64 * ACTP + 64 * TSTR + 512 + 576 + 2048) * 4 +
        3 * 64 * 4 + 256;
    cudaFuncSetAttribute(k_edge, cudaFuncAttributeMaxDynamicSharedMemorySize, edge_smem);
    k_edge<<<304, 256, edge_smem>>>(ee, sh, dst, src, Wm1, Wm2, Wm3);

    dim3 gf((NN + 63) / 64, 4);
    k_final<<<gf, 256>>>(W2, out);
}